// round 14
// baseline (speedup 1.0000x reference)
#include <cuda_runtime.h>

#define NB 16
#define NA 3
#define NM 32
#define NC 80
#define NH 80
#define NW 80
#define NHW (NH * NW)                 // 6400
#define CH (NA * (5 + NC) + NA * NM)  // 351
#define NE (NB * NA * NHW)            // 307200
#define TPB 256
#define NWARP (TPB / 32)              // 8
#define NBLK (NE / TPB)               // 1200
#define THRESH 0.05f
#define STRIDEF 8.0f
#define ROW (7 + NM)                  // 39
#define STAGE 128                     // staged rows per block (mean keep ~69)
#define LBW 4                         // lookback states per lane (window = 128)

// state word: bits[63:62] flag (0=invalid, 1=AGG, 2=PRE), bit[61] round parity,
// bits[31:0] count. Stale entries from the previous launch carry the opposite
// parity and read as not-ready; no reset kernel needed.
__device__ unsigned long long g_state[NBLK];   // zero-init at module load
__device__ int g_round = 0;

__global__ void __launch_bounds__(TPB, 7)
fused_kernel(const float* __restrict__ in, const float* __restrict__ anchors,
             float* __restrict__ out, long long out_size)
{
    __shared__ float s_stage[STAGE * ROW];     // 19968 B
    __shared__ int   s_warp[NWARP];
    __shared__ int   s_base;

    const int tid  = threadIdx.x;
    const int lane = tid & 31;
    const int wid  = tid >> 5;
    const int bid  = blockIdx.x;

    const unsigned round = (unsigned)*(volatile const int*)&g_round;

    const int e = bid * TPB + tid;
    const int b = e / (NA * NHW);
    const int r = e - b * (NA * NHW);
    const int a = r / NHW;
    const int p = r - a * NHW;

    const float* base = in + ((size_t)b * CH + (size_t)a * (5 + NC)) * NHW + p;

    // objectness load issued first: overlaps the class loop
    const float oraw = __ldg(base + 4 * NHW);

    // ---- max-free softmax, 8-wide double-buffered pipeline (R12-proven) ----
    const float* cb = base + 5 * NHW;
    float xa[8], xb[8];
#pragma unroll
    for (int i = 0; i < 8; ++i) xa[i] = __ldg(cb + i * NHW);

    float m = -1e30f, s = 0.0f;
    int idx = 0;
#pragma unroll
    for (int t = 0; t < NC / 8; ++t) {
        if (t + 1 < NC / 8) {
#pragma unroll
            for (int i = 0; i < 8; ++i) {
                float v = __ldg(cb + ((t + 1) * 8 + i) * NHW);
                if (t & 1) xa[i] = v; else xb[i] = v;
            }
        }
#pragma unroll
        for (int i = 0; i < 8; ++i) {
            float x = (t & 1) ? xb[i] : xa[i];
            s += __expf(x);
            if (x > m) { m = x; idx = t * 8 + i; }
        }
    }

    const float obj = 1.0f / (1.0f + expf(-oraw));   // accurate: threshold-critical
    const float score = obj * __expf(m) / s;
    const bool keep = score > THRESH;

    // ---- block rank ----
    const unsigned ball = __ballot_sync(0xffffffffu, keep);
    if (lane == 0) s_warp[wid] = __popc(ball);
    __syncthreads();
    int texcl = 0, total = 0;
#pragma unroll
    for (int i = 0; i < NWARP; ++i) {
        int c = s_warp[i];
        if (i < wid) texcl += c;
        total += c;
    }
    texcl += __popc(ball & ((1u << lane) - 1u));

    const unsigned long long RB   = (unsigned long long)round << 61;
    const unsigned long long AGGT = (1ull << 62) | RB;
    const unsigned long long PRET = (2ull << 62) | RB;

    // warp0 publishes AGG + resolves prefix; warps 1..7 stage rows meanwhile.
    if (wid == 0) {
        if (bid == 0) {
            if (lane == 0) {
                atomicExch(&g_state[0], PRET | (unsigned)total);
                s_base = 0;
            }
        } else {
            if (lane == 0)
                atomicExch(&g_state[bid], AGGT | (unsigned)total);
            int excl = 0;
            int j = bid - 1;
            for (;;) {
                // window of 128: lane handles offsets lane, lane+32, lane+64, lane+96
                unsigned long long v[LBW];
                bool allready;
                bool first = true;
                do {
                    if (!first) __nanosleep(40);
                    first = false;
                    allready = true;
#pragma unroll
                    for (int k = 0; k < LBW; ++k) {
                        const int gidx = j - lane - 32 * k;
                        v[k] = (gidx >= 0)
                             ? *(volatile const unsigned long long*)&g_state[gidx]
                             : PRET;
                        allready &= ((v[k] >> 62) != 0ull) &&
                                    ((unsigned)((v[k] >> 61) & 1ull) == round);
                    }
                } while (__any_sync(0xffffffffu, !allready));

                // nearest PRE (smallest offset from j)
                int myc = 32 * LBW;
#pragma unroll
                for (int k = 0; k < LBW; ++k)
                    if ((v[k] >> 62) == 2ull) { myc = lane + 32 * k; break; }
                const int cut = __reduce_min_sync(0xffffffffu, myc);

                unsigned add = 0;
#pragma unroll
                for (int k = 0; k < LBW; ++k)
                    if (lane + 32 * k <= cut) add += (unsigned)(v[k] & 0xffffffffu);
                excl += (int)__reduce_add_sync(0xffffffffu, add);

                if (cut < 32 * LBW) break;
                j -= 32 * LBW;
            }
            if (lane == 0) {
                atomicExch(&g_state[bid], PRET | (unsigned)(excl + total));
                s_base = excl;
            }
        }
        if (bid == NBLK - 1 && lane == 0)
            *(volatile int*)&g_round = (int)(round ^ 1u);
    }

    // ---- stage this thread's row into smem (overlaps warp0 lookback) ----
    if (keep && texcl < STAGE) {
        float* rowp = s_stage + texcl * ROW;

        const float x0 = __ldg(base + 0 * NHW);
        const float y0 = __ldg(base + 1 * NHW);
        const float w0 = __ldg(base + 2 * NHW);
        const float h0 = __ldg(base + 3 * NHW);

        const float aw = anchors[a * 2 + 0];
        const float ah = anchors[a * 2 + 1];
        const float amax = fmaxf(fmaxf(fmaxf(anchors[0], anchors[1]),
                                       fmaxf(anchors[2], anchors[3])),
                                 fmaxf(anchors[4], anchors[5]));
        const float maxv = floorf(logf(1e35f / amax / STRIDEF));

        rowp[0] = (float)b;
        rowp[1] = (1.0f / (1.0f + __expf(-x0)) + (float)(p % NW)) * STRIDEF;
        rowp[2] = (1.0f / (1.0f + __expf(-y0)) + (float)(p / NW)) * STRIDEF;
        rowp[3] = __expf(fminf(w0, maxv)) * aw * STRIDEF;
        rowp[4] = __expf(fminf(h0, maxv)) * ah * STRIDEF;
        rowp[5 + NM] = score;
        rowp[6 + NM] = (float)idx;

        const float* mb = in + ((size_t)b * CH + NA * (5 + NC) + (size_t)a * NM) * NHW + p;
#pragma unroll 8
        for (int mi = 0; mi < NM; ++mi)
            rowp[5 + mi] = __ldg(mb + mi * NHW);
    }
    __syncthreads();

    if (total == 0) return;
    const long long obase = (long long)s_base * ROW;

    // ---- coalesced block copy of staged rows ----
    const int nfl = (total < STAGE ? total : STAGE) * ROW;
    if (obase + nfl <= out_size) {
        for (int i = tid; i < nfl; i += TPB)
            out[obase + i] = s_stage[i];
    } else {
        for (int i = tid; i < nfl; i += TPB) {
            const long long oi = obase + i;
            if (oi < out_size) out[oi] = s_stage[i];
        }
    }

    // ---- rare overflow (>STAGE kept rows): direct scattered write ----
    if (keep && texcl >= STAGE) {
        const long long o = obase + (long long)texcl * ROW;
        if (o + ROW <= out_size) {
            const float x0 = __ldg(base + 0 * NHW);
            const float y0 = __ldg(base + 1 * NHW);
            const float w0 = __ldg(base + 2 * NHW);
            const float h0 = __ldg(base + 3 * NHW);
            const float aw = anchors[a * 2 + 0];
            const float ah = anchors[a * 2 + 1];
            const float amax = fmaxf(fmaxf(fmaxf(anchors[0], anchors[1]),
                                           fmaxf(anchors[2], anchors[3])),
                                     fmaxf(anchors[4], anchors[5]));
            const float maxv = floorf(logf(1e35f / amax / STRIDEF));
            out[o + 0] = (float)b;
            out[o + 1] = (1.0f / (1.0f + __expf(-x0)) + (float)(p % NW)) * STRIDEF;
            out[o + 2] = (1.0f / (1.0f + __expf(-y0)) + (float)(p / NW)) * STRIDEF;
            out[o + 3] = __expf(fminf(w0, maxv)) * aw * STRIDEF;
            out[o + 4] = __expf(fminf(h0, maxv)) * ah * STRIDEF;
            out[o + 5 + NM] = score;
            out[o + 6 + NM] = (float)idx;
            const float* mb = in + ((size_t)b * CH + NA * (5 + NC) + (size_t)a * NM) * NHW + p;
#pragma unroll 8
            for (int mi = 0; mi < NM; ++mi)
                out[o + 5 + mi] = __ldg(mb + mi * NHW);
        }
    }
}

extern "C" void kernel_launch(void* const* d_in, const int* in_sizes, int n_in,
                              void* d_out, int out_size)
{
    const float* in      = (const float*)d_in[0];
    const float* anchors = (const float*)d_in[1];
    float* out = (float*)d_out;

    fused_kernel<<<NBLK, TPB>>>(in, anchors, out, (long long)out_size);
}

// round 15
// speedup vs baseline: 1.0251x; 1.0251x over previous
#include <cuda_runtime.h>

#define NB 16
#define NA 3
#define NM 32
#define NC 80
#define NH 80
#define NW 80
#define NHW (NH * NW)                 // 6400
#define CH (NA * (5 + NC) + NA * NM)  // 351
#define NE (NB * NA * NHW)            // 307200
#define TPB 256
#define NWARP (TPB / 32)              // 8
#define NBLK (NE / TPB)               // 1200
#define THRESH 0.05f
#define STRIDEF 8.0f
#define ROW (7 + NM)                  // 39
#define STAGE 128                     // staged rows per block (mean keep ~69)
#define GSZ 64                        // blocks per prefix group
#define NGRP_FULL (NBLK / GSZ)        // 18 full groups (last partial group has no leader)

// state words: bit[62]=published, bit[61]=round parity, bits[31:0]=count.
// Stale entries from the previous launch carry the opposite parity and read
// as not-ready; no reset kernel needed. No PRE flag / no serial ripple:
// prefixes are assembled from direct AGG sums (2 L2 hops total).
__device__ unsigned long long g_state[NBLK];        // per-block totals
__device__ unsigned long long g_gstate[NGRP_FULL];  // per-group totals
__device__ int g_round = 0;

__global__ void __launch_bounds__(TPB, 7)
fused_kernel(const float* __restrict__ in, const float* __restrict__ anchors,
             float* __restrict__ out, long long out_size)
{
    __shared__ float s_stage[STAGE * ROW];     // 19968 B
    __shared__ int   s_warp[NWARP];
    __shared__ int   s_base;

    const int tid  = threadIdx.x;
    const int lane = tid & 31;
    const int wid  = tid >> 5;
    const int bid  = blockIdx.x;

    const unsigned round = (unsigned)*(volatile const int*)&g_round;

    const int e = bid * TPB + tid;
    const int b = e / (NA * NHW);
    const int r = e - b * (NA * NHW);
    const int a = r / NHW;
    const int p = r - a * NHW;

    const float* base = in + ((size_t)b * CH + (size_t)a * (5 + NC)) * NHW + p;

    // objectness load issued first: overlaps the class loop
    const float oraw = __ldg(base + 4 * NHW);

    // ---- max-free softmax, 8-wide double-buffered pipeline (R12-proven) ----
    const float* cb = base + 5 * NHW;
    float xa[8], xb[8];
#pragma unroll
    for (int i = 0; i < 8; ++i) xa[i] = __ldg(cb + i * NHW);

    float m = -1e30f, s = 0.0f;
    int idx = 0;
#pragma unroll
    for (int t = 0; t < NC / 8; ++t) {
        if (t + 1 < NC / 8) {
#pragma unroll
            for (int i = 0; i < 8; ++i) {
                float v = __ldg(cb + ((t + 1) * 8 + i) * NHW);
                if (t & 1) xa[i] = v; else xb[i] = v;
            }
        }
#pragma unroll
        for (int i = 0; i < 8; ++i) {
            float x = (t & 1) ? xb[i] : xa[i];
            s += __expf(x);
            if (x > m) { m = x; idx = t * 8 + i; }
        }
    }

    const float obj = 1.0f / (1.0f + expf(-oraw));   // accurate: threshold-critical
    const float score = obj * __expf(m) / s;
    const bool keep = score > THRESH;

    // ---- block rank ----
    const unsigned ball = __ballot_sync(0xffffffffu, keep);
    if (lane == 0) s_warp[wid] = __popc(ball);
    __syncthreads();
    int texcl = 0, total = 0;
#pragma unroll
    for (int i = 0; i < NWARP; ++i) {
        int c = s_warp[i];
        if (i < wid) texcl += c;
        total += c;
    }
    texcl += __popc(ball & ((1u << lane) - 1u));

    const unsigned long long RB  = (unsigned long long)round << 61;
    const unsigned long long PUB = (1ull << 62) | RB;

    // ---- hierarchical ripple-free prefix (warp 0); warps 1..7 stage rows ----
    if (wid == 0) {
        const int grp   = bid >> 6;          // group index
        const int gfirst = grp << 6;         // first bid of group

        // 1. publish own AGG
        if (lane == 0)
            atomicExch(&g_state[bid], PUB | (unsigned)total);

        // 2. sum in-group predecessors [gfirst, bid) — direct, non-chained
        unsigned sum_in = 0;
        const int nin = bid - gfirst;        // 0..63
        for (int k = lane; k < nin; k += 32) {
            unsigned long long v;
            bool first = true;
            do {
                if (!first) __nanosleep(40);
                first = false;
                v = *(volatile const unsigned long long*)&g_state[gfirst + k];
            } while (((v >> 62) == 0ull) ||
                     ((unsigned)((v >> 61) & 1ull) != round));
            sum_in += (unsigned)(v & 0xffffffffu);
        }
        const int red_in = (int)__reduce_add_sync(0xffffffffu, sum_in);

        // 3. group leader (last bid of a full group) publishes group total
        if ((bid & (GSZ - 1)) == GSZ - 1) {
            if (lane == 0)
                atomicExch(&g_gstate[grp], PUB | (unsigned)(red_in + total));
        }

        // 4. sum predecessor group totals (grp <= 18 -> one word per lane)
        unsigned sum_g = 0;
        if (lane < grp) {
            unsigned long long v;
            bool first = true;
            do {
                if (!first) __nanosleep(40);
                first = false;
                v = *(volatile const unsigned long long*)&g_gstate[lane];
            } while (((v >> 62) == 0ull) ||
                     ((unsigned)((v >> 61) & 1ull) != round));
            sum_g = (unsigned)(v & 0xffffffffu);
        }
        const int red_g = (int)__reduce_add_sync(0xffffffffu, sum_g);

        if (lane == 0) s_base = red_g + red_in;

        // Last block: its waits cover groups 0..17 and in-group 1152..1198,
        // so every block has published (hence read g_round) -> safe to flip.
        if (bid == NBLK - 1 && lane == 0)
            *(volatile int*)&g_round = (int)(round ^ 1u);
    }

    // ---- stage this thread's row into smem (overlaps warp0 prefix work) ----
    if (keep && texcl < STAGE) {
        float* rowp = s_stage + texcl * ROW;

        const float x0 = __ldg(base + 0 * NHW);
        const float y0 = __ldg(base + 1 * NHW);
        const float w0 = __ldg(base + 2 * NHW);
        const float h0 = __ldg(base + 3 * NHW);

        const float aw = anchors[a * 2 + 0];
        const float ah = anchors[a * 2 + 1];
        const float amax = fmaxf(fmaxf(fmaxf(anchors[0], anchors[1]),
                                       fmaxf(anchors[2], anchors[3])),
                                 fmaxf(anchors[4], anchors[5]));
        const float maxv = floorf(logf(1e35f / amax / STRIDEF));

        rowp[0] = (float)b;
        rowp[1] = (1.0f / (1.0f + __expf(-x0)) + (float)(p % NW)) * STRIDEF;
        rowp[2] = (1.0f / (1.0f + __expf(-y0)) + (float)(p / NW)) * STRIDEF;
        rowp[3] = __expf(fminf(w0, maxv)) * aw * STRIDEF;
        rowp[4] = __expf(fminf(h0, maxv)) * ah * STRIDEF;
        rowp[5 + NM] = score;
        rowp[6 + NM] = (float)idx;

        const float* mb = in + ((size_t)b * CH + NA * (5 + NC) + (size_t)a * NM) * NHW + p;
#pragma unroll 8
        for (int mi = 0; mi < NM; ++mi)
            rowp[5 + mi] = __ldg(mb + mi * NHW);
    }
    __syncthreads();

    if (total == 0) return;
    const long long obase = (long long)s_base * ROW;

    // ---- coalesced block copy of staged rows ----
    const int nfl = (total < STAGE ? total : STAGE) * ROW;
    if (obase + nfl <= out_size) {
        for (int i = tid; i < nfl; i += TPB)
            out[obase + i] = s_stage[i];
    } else {
        for (int i = tid; i < nfl; i += TPB) {
            const long long oi = obase + i;
            if (oi < out_size) out[oi] = s_stage[i];
        }
    }

    // ---- rare overflow (>STAGE kept rows): direct scattered write ----
    if (keep && texcl >= STAGE) {
        const long long o = obase + (long long)texcl * ROW;
        if (o + ROW <= out_size) {
            const float x0 = __ldg(base + 0 * NHW);
            const float y0 = __ldg(base + 1 * NHW);
            const float w0 = __ldg(base + 2 * NHW);
            const float h0 = __ldg(base + 3 * NHW);
            const float aw = anchors[a * 2 + 0];
            const float ah = anchors[a * 2 + 1];
            const float amax = fmaxf(fmaxf(fmaxf(anchors[0], anchors[1]),
                                           fmaxf(anchors[2], anchors[3])),
                                     fmaxf(anchors[4], anchors[5]));
            const float maxv = floorf(logf(1e35f / amax / STRIDEF));
            out[o + 0] = (float)b;
            out[o + 1] = (1.0f / (1.0f + __expf(-x0)) + (float)(p % NW)) * STRIDEF;
            out[o + 2] = (1.0f / (1.0f + __expf(-y0)) + (float)(p / NW)) * STRIDEF;
            out[o + 3] = __expf(fminf(w0, maxv)) * aw * STRIDEF;
            out[o + 4] = __expf(fminf(h0, maxv)) * ah * STRIDEF;
            out[o + 5 + NM] = score;
            out[o + 6 + NM] = (float)idx;
            const float* mb = in + ((size_t)b * CH + NA * (5 + NC) + (size_t)a * NM) * NHW + p;
#pragma unroll 8
            for (int mi = 0; mi < NM; ++mi)
                out[o + 5 + mi] = __ldg(mb + mi * NHW);
        }
    }
}

extern "C" void kernel_launch(void* const* d_in, const int* in_sizes, int n_in,
                              void* d_out, int out_size)
{
    const float* in      = (const float*)d_in[0];
    const float* anchors = (const float*)d_in[1];
    float* out = (float*)d_out;

    fused_kernel<<<NBLK, TPB>>>(in, anchors, out, (long long)out_size);
}

// round 16
// speedup vs baseline: 1.0626x; 1.0366x over previous
#include <cuda_runtime.h>

#define NB 16
#define NA 3
#define NM 32
#define NC 80
#define NH 80
#define NW 80
#define NHW (NH * NW)                 // 6400
#define CH (NA * (5 + NC) + NA * NM)  // 351
#define NE (NB * NA * NHW)            // 307200
#define TPB 256
#define NWARP (TPB / 32)              // 8
#define NBLK (NE / TPB)               // 1200
#define THRESH 0.05f
#define STRIDEF 8.0f
#define ROW (7 + NM)                  // 39
#define STAGE 128                     // staged rows per block (mean keep ~69)
#define GSZ 64                        // blocks per prefix group
#define NGRP_FULL (NBLK / GSZ)        // 18 full groups (last partial group has no leader)

// state words: bit[62]=published, bit[61]=round parity, bits[31:0]=count.
// Stale entries from the previous launch carry the opposite parity and read
// as not-ready; no reset kernel needed. No PRE flag / no serial ripple:
// prefixes are assembled from direct AGG sums (2 L2 hops total).
__device__ unsigned long long g_state[NBLK];        // per-block totals
__device__ unsigned long long g_gstate[NGRP_FULL];  // per-group totals
__device__ int g_round = 0;

__global__ void __launch_bounds__(TPB, 7)
fused_kernel(const float* __restrict__ in, const float* __restrict__ anchors,
             float* __restrict__ out, long long out_size)
{
    __shared__ float s_stage[STAGE * ROW];     // 19968 B
    __shared__ int   s_warp[NWARP];
    __shared__ int   s_base;

    const int tid  = threadIdx.x;
    const int lane = tid & 31;
    const int wid  = tid >> 5;
    const int bid  = blockIdx.x;

    const unsigned round = (unsigned)*(volatile const int*)&g_round;

    const int e = bid * TPB + tid;
    const int b = e / (NA * NHW);
    const int r = e - b * (NA * NHW);
    const int a = r / NHW;
    const int p = r - a * NHW;

    const float* base = in + ((size_t)b * CH + (size_t)a * (5 + NC)) * NHW + p;

    // objectness load issued first: overlaps the class loop
    const float oraw = __ldcs(base + 4 * NHW);

    // ---- max-free softmax, 8-wide double-buffered pipeline, 2 accumulators ----
    const float* cb = base + 5 * NHW;
    float xa[8], xb[8];
#pragma unroll
    for (int i = 0; i < 8; ++i) xa[i] = __ldcs(cb + i * NHW);

    float m = -1e30f, s0 = 0.0f, s1 = 0.0f;
    int idx = 0;
#pragma unroll
    for (int t = 0; t < NC / 8; ++t) {
        if (t + 1 < NC / 8) {
#pragma unroll
            for (int i = 0; i < 8; ++i) {
                float v = __ldcs(cb + ((t + 1) * 8 + i) * NHW);
                if (t & 1) xa[i] = v; else xb[i] = v;
            }
        }
#pragma unroll
        for (int i = 0; i < 8; ++i) {
            float x = (t & 1) ? xb[i] : xa[i];
            if (i & 1) s1 += __expf(x); else s0 += __expf(x);
            if (x > m) { m = x; idx = t * 8 + i; }
        }
    }
    const float s = s0 + s1;

    const float obj = 1.0f / (1.0f + expf(-oraw));   // accurate: threshold-critical
    const float score = obj * __expf(m) / s;
    const bool keep = score > THRESH;

    // ---- block rank ----
    const unsigned ball = __ballot_sync(0xffffffffu, keep);
    if (lane == 0) s_warp[wid] = __popc(ball);
    __syncthreads();
    int texcl = 0, total = 0;
#pragma unroll
    for (int i = 0; i < NWARP; ++i) {
        int c = s_warp[i];
        if (i < wid) texcl += c;
        total += c;
    }
    texcl += __popc(ball & ((1u << lane) - 1u));

    const unsigned long long RB  = (unsigned long long)round << 61;
    const unsigned long long PUB = (1ull << 62) | RB;

    // ---- hierarchical ripple-free prefix (warp 0); warps 1..7 stage rows ----
    if (wid == 0) {
        const int grp    = bid >> 6;         // group index
        const int gfirst = grp << 6;         // first bid of group

        // 1. publish own AGG
        if (lane == 0)
            atomicExch(&g_state[bid], PUB | (unsigned)total);

        // 2. sum in-group predecessors [gfirst, bid) — direct, non-chained
        unsigned sum_in = 0;
        const int nin = bid - gfirst;        // 0..63
        for (int k = lane; k < nin; k += 32) {
            unsigned long long v;
            bool first = true;
            do {
                if (!first) __nanosleep(40);
                first = false;
                v = *(volatile const unsigned long long*)&g_state[gfirst + k];
            } while (((v >> 62) == 0ull) ||
                     ((unsigned)((v >> 61) & 1ull) != round));
            sum_in += (unsigned)(v & 0xffffffffu);
        }
        const int red_in = (int)__reduce_add_sync(0xffffffffu, sum_in);

        // 3. group leader (last bid of a full group) publishes group total
        if ((bid & (GSZ - 1)) == GSZ - 1) {
            if (lane == 0)
                atomicExch(&g_gstate[grp], PUB | (unsigned)(red_in + total));
        }

        // 4. sum predecessor group totals (grp <= 18 -> one word per lane)
        unsigned sum_g = 0;
        if (lane < grp) {
            unsigned long long v;
            bool first = true;
            do {
                if (!first) __nanosleep(40);
                first = false;
                v = *(volatile const unsigned long long*)&g_gstate[lane];
            } while (((v >> 62) == 0ull) ||
                     ((unsigned)((v >> 61) & 1ull) != round));
            sum_g = (unsigned)(v & 0xffffffffu);
        }
        const int red_g = (int)__reduce_add_sync(0xffffffffu, sum_g);

        if (lane == 0) s_base = red_g + red_in;

        // Last block: its waits cover groups 0..17 and in-group 1152..1198,
        // so every block has published (hence read g_round) -> safe to flip.
        if (bid == NBLK - 1 && lane == 0)
            *(volatile int*)&g_round = (int)(round ^ 1u);
    }

    // ---- stage this thread's row into smem (overlaps warp0 prefix work) ----
    if (keep && texcl < STAGE) {
        float* rowp = s_stage + texcl * ROW;

        const float x0 = __ldcs(base + 0 * NHW);
        const float y0 = __ldcs(base + 1 * NHW);
        const float w0 = __ldcs(base + 2 * NHW);
        const float h0 = __ldcs(base + 3 * NHW);

        const float aw = anchors[a * 2 + 0];
        const float ah = anchors[a * 2 + 1];
        const float amax = fmaxf(fmaxf(fmaxf(anchors[0], anchors[1]),
                                       fmaxf(anchors[2], anchors[3])),
                                 fmaxf(anchors[4], anchors[5]));
        const float maxv = floorf(logf(1e35f / amax / STRIDEF));

        rowp[0] = (float)b;
        rowp[1] = (1.0f / (1.0f + __expf(-x0)) + (float)(p % NW)) * STRIDEF;
        rowp[2] = (1.0f / (1.0f + __expf(-y0)) + (float)(p / NW)) * STRIDEF;
        rowp[3] = __expf(fminf(w0, maxv)) * aw * STRIDEF;
        rowp[4] = __expf(fminf(h0, maxv)) * ah * STRIDEF;
        rowp[5 + NM] = score;
        rowp[6 + NM] = (float)idx;

        const float* mb = in + ((size_t)b * CH + NA * (5 + NC) + (size_t)a * NM) * NHW + p;
#pragma unroll 8
        for (int mi = 0; mi < NM; ++mi)
            rowp[5 + mi] = __ldcs(mb + mi * NHW);
    }
    __syncthreads();

    if (total == 0) return;
    const long long obase = (long long)s_base * ROW;

    // ---- coalesced block copy of staged rows ----
    const int nfl = (total < STAGE ? total : STAGE) * ROW;
    if (obase + nfl <= out_size) {
        for (int i = tid; i < nfl; i += TPB)
            out[obase + i] = s_stage[i];
    } else {
        for (int i = tid; i < nfl; i += TPB) {
            const long long oi = obase + i;
            if (oi < out_size) out[oi] = s_stage[i];
        }
    }

    // ---- rare overflow (>STAGE kept rows): direct scattered write ----
    if (keep && texcl >= STAGE) {
        const long long o = obase + (long long)texcl * ROW;
        if (o + ROW <= out_size) {
            const float x0 = __ldcs(base + 0 * NHW);
            const float y0 = __ldcs(base + 1 * NHW);
            const float w0 = __ldcs(base + 2 * NHW);
            const float h0 = __ldcs(base + 3 * NHW);
            const float aw = anchors[a * 2 + 0];
            const float ah = anchors[a * 2 + 1];
            const float amax = fmaxf(fmaxf(fmaxf(anchors[0], anchors[1]),
                                           fmaxf(anchors[2], anchors[3])),
                                     fmaxf(anchors[4], anchors[5]));
            const float maxv = floorf(logf(1e35f / amax / STRIDEF));
            out[o + 0] = (float)b;
            out[o + 1] = (1.0f / (1.0f + __expf(-x0)) + (float)(p % NW)) * STRIDEF;
            out[o + 2] = (1.0f / (1.0f + __expf(-y0)) + (float)(p / NW)) * STRIDEF;
            out[o + 3] = __expf(fminf(w0, maxv)) * aw * STRIDEF;
            out[o + 4] = __expf(fminf(h0, maxv)) * ah * STRIDEF;
            out[o + 5 + NM] = score;
            out[o + 6 + NM] = (float)idx;
            const float* mb = in + ((size_t)b * CH + NA * (5 + NC) + (size_t)a * NM) * NHW + p;
#pragma unroll 8
            for (int mi = 0; mi < NM; ++mi)
                out[o + 5 + mi] = __ldcs(mb + mi * NHW);
        }
    }
}

extern "C" void kernel_launch(void* const* d_in, const int* in_sizes, int n_in,
                              void* d_out, int out_size)
{
    const float* in      = (const float*)d_in[0];
    const float* anchors = (const float*)d_in[1];
    float* out = (float*)d_out;

    fused_kernel<<<NBLK, TPB>>>(in, anchors, out, (long long)out_size);
}

// round 17
// speedup vs baseline: 1.0750x; 1.0117x over previous
#include <cuda_runtime.h>
#include <cstdint>

#define NB 16
#define NA 3
#define NM 32
#define NC 80
#define NH 80
#define NW 80
#define NHW (NH * NW)                 // 6400
#define CH (NA * (5 + NC) + NA * NM)  // 351
#define NE (NB * NA * NHW)            // 307200
#define TPB 256
#define NWARP (TPB / 32)              // 8
#define NBLK (NE / TPB)               // 1200
#define THRESH 0.05f
#define STRIDEF 8.0f
#define ROW (7 + NM)                  // 39
#define STAGE 128                     // staged rows per block (mean keep ~69)
#define GSZ 64                        // blocks per prefix group
#define NGRP_FULL (NBLK / GSZ)        // 18 full groups
#define CPC 8                         // channels per cp.async chunk
#define NCHUNK (NC / CPC)             // 10
#define PDEPTH 3                      // pipeline slots (2 chunks in flight)

// state words: bit[62]=published, bit[61]=round parity, bits[31:0]=count.
// Stale entries from the previous launch carry the opposite parity and read
// as not-ready; no reset kernel needed. Prefixes are assembled from direct
// AGG sums (2 L2 hops, no serial ripple).
__device__ unsigned long long g_state[NBLK];        // per-block totals
__device__ unsigned long long g_gstate[NGRP_FULL];  // per-group totals
__device__ int g_round = 0;

__global__ void __launch_bounds__(TPB, 8)
fused_kernel(const float* __restrict__ in, const float* __restrict__ anchors,
             float* __restrict__ out, long long out_size)
{
    // class-logit pipeline (24576 B) overlays the output staging buffer:
    // pipe is fully consumed before any stage write (rank barrier orders them).
    __shared__ __align__(16) union {
        float pipe[PDEPTH][CPC * TPB];   // 3 x 8KB
        float stage[STAGE * ROW];        // 19968 B
    } u;
    __shared__ int s_warp[NWARP];
    __shared__ int s_base;

    const int tid  = threadIdx.x;
    const int lane = tid & 31;
    const int wid  = tid >> 5;
    const int bid  = blockIdx.x;

    const unsigned round = (unsigned)*(volatile const int*)&g_round;

    // block-uniform (b, a, p_blk): 256 | NHW so a block never crosses (b,a)
    const int eb    = bid * TPB;
    const int b     = eb / (NA * NHW);
    const int rblk  = eb - b * (NA * NHW);
    const int a     = rblk / NHW;
    const int p_blk = rblk - a * NHW;
    const int p     = p_blk + tid;

    const float* base  = in + ((size_t)b * CH + (size_t)a * (5 + NC)) * NHW + p;
    const float* cbase = in + ((size_t)b * CH + (size_t)a * (5 + NC) + 5) * NHW + p_blk;

    // objectness load issued first: overlaps the whole pipeline
    const float oraw = __ldcs(base + 4 * NHW);

    // ---- cp.async chunk issue: 8 channels x 1KB, 2x16B per thread ----
    const uint32_t pipe_s = (uint32_t)__cvta_generic_to_shared(&u.pipe[0][0]);
#define ISSUE_CHUNK(K, SLOT)                                                     \
    {                                                                            \
        _Pragma("unroll")                                                        \
        for (int q = 0; q < 2; ++q) {                                            \
            const int seg = tid + q * TPB;            /* 0..511 */               \
            const int ch  = seg >> 6;                 /* 0..7  */                \
            const int col = (seg & 63) << 2;          /* 0..252 */               \
            const float* src = cbase + (size_t)((K) * CPC + ch) * NHW + col;     \
            const uint32_t dst = pipe_s +                                        \
                (uint32_t)(((SLOT) * CPC + ch) * TPB + col) * 4u;                \
            asm volatile("cp.async.cg.shared.global [%0], [%1], 16;"             \
                         :: "r"(dst), "l"(src) : "memory");                      \
        }                                                                        \
        asm volatile("cp.async.commit_group;" ::: "memory");                     \
    }

    // prologue: chunks 0,1 in flight
    ISSUE_CHUNK(0, 0)
    ISSUE_CHUNK(1, 1)

    // ---- max-free softmax over the smem pipeline ----
    float m = -1e30f, s0 = 0.0f, s1 = 0.0f;
    int idx = 0;
#pragma unroll
    for (int t = 0; t < NCHUNK; ++t) {
        if (t == NCHUNK - 1) asm volatile("cp.async.wait_group 0;" ::: "memory");
        else                 asm volatile("cp.async.wait_group 1;" ::: "memory");
        __syncthreads();   // chunk t visible to all; slot (t+2)%3 free for reuse
        if (t + 2 < NCHUNK) ISSUE_CHUNK(t + 2, (t + 2) % PDEPTH)
        const float* buf = &u.pipe[t % PDEPTH][0];
#pragma unroll
        for (int i = 0; i < CPC; ++i) {
            float x = buf[i * TPB + tid];
            if (i & 1) s1 += __expf(x); else s0 += __expf(x);
            if (x > m) { m = x; idx = t * CPC + i; }
        }
    }
    const float s = s0 + s1;

    const float obj = 1.0f / (1.0f + expf(-oraw));   // accurate: threshold-critical
    const float score = obj * __expf(m) / s;
    const bool keep = score > THRESH;

    // ---- block rank ----
    const unsigned ball = __ballot_sync(0xffffffffu, keep);
    if (lane == 0) s_warp[wid] = __popc(ball);
    __syncthreads();   // also orders: pipe reads above before stage writes below
    int texcl = 0, total = 0;
#pragma unroll
    for (int i = 0; i < NWARP; ++i) {
        int c = s_warp[i];
        if (i < wid) texcl += c;
        total += c;
    }
    texcl += __popc(ball & ((1u << lane) - 1u));

    const unsigned long long RB  = (unsigned long long)round << 61;
    const unsigned long long PUB = (1ull << 62) | RB;

    // ---- hierarchical ripple-free prefix (warp 0); warps 1..7 stage rows ----
    if (wid == 0) {
        const int grp    = bid >> 6;
        const int gfirst = grp << 6;

        if (lane == 0)
            atomicExch(&g_state[bid], PUB | (unsigned)total);

        unsigned sum_in = 0;
        const int nin = bid - gfirst;        // 0..63
        for (int k = lane; k < nin; k += 32) {
            unsigned long long v;
            bool first = true;
            do {
                if (!first) __nanosleep(40);
                first = false;
                v = *(volatile const unsigned long long*)&g_state[gfirst + k];
            } while (((v >> 62) == 0ull) ||
                     ((unsigned)((v >> 61) & 1ull) != round));
            sum_in += (unsigned)(v & 0xffffffffu);
        }
        const int red_in = (int)__reduce_add_sync(0xffffffffu, sum_in);

        if ((bid & (GSZ - 1)) == GSZ - 1) {
            if (lane == 0)
                atomicExch(&g_gstate[bid >> 6], PUB | (unsigned)(red_in + total));
        }

        unsigned sum_g = 0;
        if (lane < grp) {
            unsigned long long v;
            bool first = true;
            do {
                if (!first) __nanosleep(40);
                first = false;
                v = *(volatile const unsigned long long*)&g_gstate[lane];
            } while (((v >> 62) == 0ull) ||
                     ((unsigned)((v >> 61) & 1ull) != round));
            sum_g = (unsigned)(v & 0xffffffffu);
        }
        const int red_g = (int)__reduce_add_sync(0xffffffffu, sum_g);

        if (lane == 0) s_base = red_g + red_in;

        if (bid == NBLK - 1 && lane == 0)
            *(volatile int*)&g_round = (int)(round ^ 1u);
    }

    // ---- stage this thread's row into smem (overlaps warp0 prefix work) ----
    if (keep && texcl < STAGE) {
        float* rowp = u.stage + texcl * ROW;

        const float x0 = __ldcs(base + 0 * NHW);
        const float y0 = __ldcs(base + 1 * NHW);
        const float w0 = __ldcs(base + 2 * NHW);
        const float h0 = __ldcs(base + 3 * NHW);

        const float aw = anchors[a * 2 + 0];
        const float ah = anchors[a * 2 + 1];
        const float amax = fmaxf(fmaxf(fmaxf(anchors[0], anchors[1]),
                                       fmaxf(anchors[2], anchors[3])),
                                 fmaxf(anchors[4], anchors[5]));
        const float maxv = floorf(logf(1e35f / amax / STRIDEF));

        rowp[0] = (float)b;
        rowp[1] = (1.0f / (1.0f + __expf(-x0)) + (float)(p % NW)) * STRIDEF;
        rowp[2] = (1.0f / (1.0f + __expf(-y0)) + (float)(p / NW)) * STRIDEF;
        rowp[3] = __expf(fminf(w0, maxv)) * aw * STRIDEF;
        rowp[4] = __expf(fminf(h0, maxv)) * ah * STRIDEF;
        rowp[5 + NM] = score;
        rowp[6 + NM] = (float)idx;

        const float* mb = in + ((size_t)b * CH + NA * (5 + NC) + (size_t)a * NM) * NHW + p;
#pragma unroll 8
        for (int mi = 0; mi < NM; ++mi)
            rowp[5 + mi] = __ldcs(mb + mi * NHW);
    }
    __syncthreads();

    if (total == 0) return;
    const long long obase = (long long)s_base * ROW;

    // ---- coalesced block copy of staged rows ----
    const int nfl = (total < STAGE ? total : STAGE) * ROW;
    if (obase + nfl <= out_size) {
        for (int i = tid; i < nfl; i += TPB)
            out[obase + i] = u.stage[i];
    } else {
        for (int i = tid; i < nfl; i += TPB) {
            const long long oi = obase + i;
            if (oi < out_size) out[oi] = u.stage[i];
        }
    }

    // ---- rare overflow (>STAGE kept rows): direct scattered write ----
    if (keep && texcl >= STAGE) {
        const long long o = obase + (long long)texcl * ROW;
        if (o + ROW <= out_size) {
            const float x0 = __ldcs(base + 0 * NHW);
            const float y0 = __ldcs(base + 1 * NHW);
            const float w0 = __ldcs(base + 2 * NHW);
            const float h0 = __ldcs(base + 3 * NHW);
            const float aw = anchors[a * 2 + 0];
            const float ah = anchors[a * 2 + 1];
            const float amax = fmaxf(fmaxf(fmaxf(anchors[0], anchors[1]),
                                           fmaxf(anchors[2], anchors[3])),
                                     fmaxf(anchors[4], anchors[5]));
            const float maxv = floorf(logf(1e35f / amax / STRIDEF));
            out[o + 0] = (float)b;
            out[o + 1] = (1.0f / (1.0f + __expf(-x0)) + (float)(p % NW)) * STRIDEF;
            out[o + 2] = (1.0f / (1.0f + __expf(-y0)) + (float)(p / NW)) * STRIDEF;
            out[o + 3] = __expf(fminf(w0, maxv)) * aw * STRIDEF;
            out[o + 4] = __expf(fminf(h0, maxv)) * ah * STRIDEF;
            out[o + 5 + NM] = score;
            out[o + 6 + NM] = (float)idx;
            const float* mb = in + ((size_t)b * CH + NA * (5 + NC) + (size_t)a * NM) * NHW + p;
#pragma unroll 8
            for (int mi = 0; mi < NM; ++mi)
                out[o + 5 + mi] = __ldcs(mb + mi * NHW);
        }
    }
}

extern "C" void kernel_launch(void* const* d_in, const int* in_sizes, int n_in,
                              void* d_out, int out_size)
{
    const float* in      = (const float*)d_in[0];
    const float* anchors = (const float*)d_in[1];
    float* out = (float*)d_out;

    fused_kernel<<<NBLK, TPB>>>(in, anchors, out, (long long)out_size);
}